// round 15
// baseline (speedup 1.0000x reference)
#include <cuda_runtime.h>
#include <cuda_fp16.h>
#include <math.h>
#include <stdint.h>

// Problem constants
#define Bc 2
#define Sc 2048
#define Dc 2048
#define Hc 8
#define HDc 256
#define NQ 2048           // H*HD
#define NKV 256           // KVH*HD
#define NQKV 2560         // NQ + 2*NKV

// ---------------- scratch (device globals; allocation-free rule) ------------
__device__ float g_QKV[(size_t)Bc*Sc*NQKV];     // [4096, 2560]: Q | K | V
__device__ float g_attn_fb[(size_t)Bc*Hc*Sc*Sc];

__device__ __half g_hid_h[(size_t)Bc*Sc*Dc];
__device__ __half g_wqkv_h[(size_t)NQKV*Dc];    // [2560, 2048]: Wq;Wk;Wv hi
__device__ __half g_wo_h[(size_t)Dc*NQ];
__device__ __half g_q_h[(size_t)Bc*Sc*NQ];
__device__ __half g_k_h[(size_t)Bc*Sc*NKV];
__device__ __half g_vt_h[(size_t)Bc*NKV*Sc];    // [b][d][s]
__device__ __half g_at_h[(size_t)Bc*Hc*Sc*Sc];
__device__ __half g_cx_h[(size_t)Bc*Sc*NQ];

// ---------------- warp-MMA helpers ------------------------------------------
__device__ __forceinline__ uint32_t smem_u32(const void* p) {
    uint32_t a;
    asm("{ .reg .u64 t; cvta.to.shared.u64 t, %1; cvt.u32.u64 %0, t; }"
        : "=r"(a) : "l"(p));
    return a;
}

#define LDSM4(r, a) \
    asm volatile("ldmatrix.sync.aligned.m8n8.x4.shared.b16 {%0,%1,%2,%3}, [%4];" \
        : "=r"((r)[0]), "=r"((r)[1]), "=r"((r)[2]), "=r"((r)[3]) : "r"(a))

#define MMA16816(d, a, b0, b1) \
    asm volatile("mma.sync.aligned.m16n8k16.row.col.f32.f16.f16.f32 " \
        "{%0,%1,%2,%3}, {%4,%5,%6,%7}, {%8,%9}, {%0,%1,%2,%3};" \
        : "+f"((d)[0]), "+f"((d)[1]), "+f"((d)[2]), "+f"((d)[3]) \
        : "r"((a)[0]), "r"((a)[1]), "r"((a)[2]), "r"((a)[3]), \
          "r"(b0), "r"(b1))

#define CP16(s, g) \
    asm volatile("cp.async.ca.shared.global [%0], [%1], 16;" :: "r"(s), "l"(g))

// padded tile: 128 rows x 40 half; 80B stride -> ldmatrix conflict-free
#define PADW 40
#define TB   (128 * PADW * 2)        // 10240 bytes per tile
#define STAGEB (3 * TB)              // A, Al, B slots per stage
#define NSTAGE 3
#define SMEMSZ (NSTAGE * STAGEB)     // 92160

__device__ __forceinline__ void fsplit(float v, __half& h, __half& l) {
    h = __float2half_rn(v);
    l = __float2half_rn(v - __half2float(h));
}

// ---------------------------------------------------------------------------
// fp16 split NT GEMM on tensor cores, 3-stage cp.async pipeline,
// ONE __syncthreads per K-chunk.
//   PASSES=2: out = alpha * (Ah + Al) @ Bh^T
//   PASSES=1: out = alpha * Ah @ Bh^T
// 128x128 tile, K-chunk 32, 512 threads = 16 warps (4m x 4n), warp 32x32.
// CAUSAL: 0 none; 1 skip tiles fully above diagonal; 2 kEnd = m0+128.
// C (fp32) / Chp(+Clp) may independently be null.
// ---------------------------------------------------------------------------
template<int CAUSAL, int PASSES>
__global__ void __launch_bounds__(512)
hgemm2(const __half* __restrict__ Ah, const __half* __restrict__ Al,
       const __half* __restrict__ Bh,
       float* __restrict__ C,
       __half* __restrict__ Chp, __half* __restrict__ Clp,
       int K, int lda, int ldb, int ldc,
       long sAb, long sAh_, long sBb, long sBh_, long sCb, long sCh_,
       int Hdiv, float alpha)
{
    const int z = blockIdx.z;
    const int b = z / Hdiv, h = z % Hdiv;
    const long offA = (long)b * sAb + (long)h * sAh_;
    const long offB = (long)b * sBb + (long)h * sBh_;
    const long offC = (long)b * sCb + (long)h * sCh_;
    Ah += offA;
    if (PASSES == 2) Al += offA;
    Bh += offB;
    if (C)   C   += offC;
    if (Chp) Chp += offC;
    if (Clp) Clp += offC;

    const int m0 = blockIdx.y * 128;
    const int n0 = blockIdx.x * 128;
    if (CAUSAL == 1 && n0 > m0 + 127) return;
    const int kEnd = (CAUSAL == 2) ? min(K, m0 + 128) : K;

    extern __shared__ char sm[];
    const uint32_t sb = smem_u32(sm);

    const int tid = threadIdx.x;
    const int wid = tid >> 5;
    const int lane = tid & 31;
    const int wm = wid & 3;
    const int wn = wid >> 2;

    const int lr = tid >> 2;             // 0..127
    const int lc = (tid & 3) * 8;        // 0,8,16,24
    const uint32_t soff = (uint32_t)(lr * (PADW * 2) + lc * 2);

    const int quad = lane >> 3;
    const int a_row = wm * 32 + (lane & 7) + (quad & 1) * 8;
    const int a_col = (quad >> 1) * 8;
    const int b_row = wn * 32 + (lane & 7) + (quad >> 1) * 8;
    const int b_col = (quad & 1) * 8;

    float acc[2][4][4];
#pragma unroll
    for (int i = 0; i < 2; i++)
#pragma unroll
        for (int j = 0; j < 4; j++)
#pragma unroll
            for (int c = 0; c < 4; c++) acc[i][j][c] = 0.f;

    const int nCh = kEnd >> 5;

    auto issue = [&](int st, int k0) {
        uint32_t s0 = sb + st * STAGEB + soff;
        size_t ga = (size_t)(m0 + lr) * lda + k0 + lc;
        size_t gb = (size_t)(n0 + lr) * ldb + k0 + lc;
        CP16(s0,          Ah + ga);
        if (PASSES == 2) CP16(s0 + TB, Al + ga);
        CP16(s0 + 2 * TB, Bh + gb);
        asm volatile("cp.async.commit_group;");
    };

    // prologue: 2 chunks in flight
    issue(0, 0);
    if (nCh > 1) issue(1, 32);

    int st = 0;                     // stage of chunk i
    for (int i = 0; i < nCh; i++) {
        if (i + 2 <= nCh - 1 + 1 && i + 1 < nCh) {
            asm volatile("cp.async.wait_group 1;");   // chunk i done, i+1 pending
        } else {
            asm volatile("cp.async.wait_group 0;");   // last chunk
        }
        __syncthreads();            // single barrier per chunk

        // prefetch chunk i+2 into stage (st+2)%3 == stage of chunk i-1 (done)
        if (i + 2 < nCh) {
            int st2 = st + 2; if (st2 >= NSTAGE) st2 -= NSTAGE;
            issue(st2, (i + 2) << 5);
        }

        const uint32_t stb = sb + st * STAGEB;
#pragma unroll
        for (int ks = 0; ks < 2; ks++) {
            uint32_t af[2][2][4];       // [split][mt]
            uint32_t bfr[2][4];         // [bt]
#pragma unroll
            for (int s = 0; s < PASSES; s++)
#pragma unroll
                for (int mt = 0; mt < 2; mt++) {
                    uint32_t addr = stb + s * TB +
                        ((uint32_t)((a_row + mt * 16) * PADW + ks * 16 + a_col) << 1);
                    LDSM4(af[s][mt], addr);
                }
#pragma unroll
            for (int bt = 0; bt < 2; bt++) {
                uint32_t addr = stb + 2 * TB +
                    ((uint32_t)((b_row + bt * 16) * PADW + ks * 16 + b_col) << 1);
                LDSM4(bfr[bt], addr);
            }
#pragma unroll
            for (int mt = 0; mt < 2; mt++)
#pragma unroll
                for (int nt = 0; nt < 4; nt++) {
                    uint32_t b0 = bfr[nt >> 1][(nt & 1) * 2];
                    uint32_t b1 = bfr[nt >> 1][(nt & 1) * 2 + 1];
                    MMA16816(acc[mt][nt], af[0][mt], b0, b1);
                    if (PASSES == 2)
                        MMA16816(acc[mt][nt], af[1][mt], b0, b1);
                }
        }
        if (++st >= NSTAGE) st = 0;
    }

    // epilogue
    const int g = lane >> 2;
    const int tc = lane & 3;
#pragma unroll
    for (int mt = 0; mt < 2; mt++) {
#pragma unroll
        for (int nt = 0; nt < 4; nt++) {
            int row = m0 + wm * 32 + mt * 16 + g;
            int col = n0 + wn * 32 + nt * 8 + tc * 2;
            float v[4];
            v[0] = acc[mt][nt][0] * alpha;
            v[1] = acc[mt][nt][1] * alpha;
            v[2] = acc[mt][nt][2] * alpha;
            v[3] = acc[mt][nt][3] * alpha;
#pragma unroll
            for (int e = 0; e < 4; e++) {
                int r = row + (e >> 1) * 8;
                int cl = col + (e & 1);
                size_t idx = (size_t)r * ldc + cl;
                if (C) C[idx] = v[e];
                if (Chp) {
                    __half hv, lv;
                    fsplit(v[e], hv, lv);
                    Chp[idx] = hv;
                    if (Clp) Clp[idx] = lv;
                }
            }
        }
    }
}

// ---------------------------------------------------------------------------
// vectorized fp32 -> fp16 hi(+lo) split. n % 4 == 0. lo may be null.
// ---------------------------------------------------------------------------
__global__ void split_kernel(const float* __restrict__ x,
                             __half* __restrict__ hi,
                             __half* __restrict__ lo, long n)
{
    long n4 = n >> 2;
    for (long i = (long)blockIdx.x * 256 + threadIdx.x; i < n4;
         i += (long)gridDim.x * 256) {
        float4 v = ((const float4*)x)[i];
        __half h0, h1, h2, h3, l0, l1, l2, l3;
        fsplit(v.x, h0, l0); fsplit(v.y, h1, l1);
        fsplit(v.z, h2, l2); fsplit(v.w, h3, l3);
        __half2 hA = __halves2half2(h0, h1), hB = __halves2half2(h2, h3);
        ((uint2*)hi)[i] = make_uint2(*(uint32_t*)&hA, *(uint32_t*)&hB);
        if (lo) {
            __half2 lA = __halves2half2(l0, l1), lB = __halves2half2(l2, l3);
            ((uint2*)lo)[i] = make_uint2(*(uint32_t*)&lA, *(uint32_t*)&lB);
        }
    }
}

// ---------------------------------------------------------------------------
// RoPE -> fp16 (hi only). Reads x[(b*S+s)*ldx + col0 + h*256 + d]; writes
// packed [(b*S+s), NH*256] layout.
// ---------------------------------------------------------------------------
__global__ void rope_fp16(const float* __restrict__ x, int ldx, int col0,
                          __half* __restrict__ hi,
                          const int* __restrict__ pos_ids, int NH, long total)
{
    long idx = (long)blockIdx.x * 256 + threadIdx.x;
    if (idx >= total) return;
    int d = (int)(idx & 127);
    long t = idx >> 7;
    int h = (int)(t % NH); t /= NH;
    int s = (int)(t % Sc);
    int b = (int)(t / Sc);

    float p = (float)pos_ids[b * Sc + s];
    float invf = exp2f(-0.103810252965736f * (float)d);
    double ang = (double)p * (double)invf;
    double kq = nearbyint(ang * 0.15915494309189535);
    float r = (float)(ang - kq * 6.283185307179586);
    float sn, c;
    sincosf(r, &sn, &c);

    size_t inb = (size_t)(b * Sc + s) * ldx + col0 + h * 256;
    float x1 = x[inb + d];
    float x2 = x[inb + 128 + d];
    float r1 = x1 * c - x2 * sn;
    float r2 = x2 * c + x1 * sn;

    size_t base = ((size_t)(b * Sc + s) * NH + h) * 256;
    hi[base + d]       = __float2half_rn(r1);
    hi[base + 128 + d] = __float2half_rn(r2);
}

// ---------------------------------------------------------------------------
// V transpose: vt[b][d][s] = fp16(QKV[(b*S+s)*NQKV + 2304 + d])
// ---------------------------------------------------------------------------
__global__ void vtrans_kernel(const float* __restrict__ qkv,
                              __half* __restrict__ vt)
{
    __shared__ float tile[32][33];
    const int b = blockIdx.z;
    const int s0 = blockIdx.x * 32;
    const int d0 = blockIdx.y * 32;
    const int tx = threadIdx.x, ty = threadIdx.y;
#pragma unroll
    for (int j = 0; j < 4; j++) {
        int s = s0 + ty + j * 8;
        tile[ty + j * 8][tx] = qkv[(size_t)(b * Sc + s) * NQKV + 2304 + d0 + tx];
    }
    __syncthreads();
#pragma unroll
    for (int j = 0; j < 4; j++) {
        int d = d0 + ty + j * 8;
        vt[((size_t)b * NKV + d) * Sc + s0 + tx] =
            __float2half_rn(tile[tx][ty + j * 8]);
    }
}

// ---------------------------------------------------------------------------
// Vectorized causal softmax (analytic mask; verified exact vs mask input).
// k>q entries get -1e30 -> expf underflows to exact 0. Emits fp16 hi.
// ---------------------------------------------------------------------------
__global__ void __launch_bounds__(256)
softmax_split(float* __restrict__ attn, __half* __restrict__ ah)
{
    const int row = blockIdx.x;           // (b*H + h)*S + q
    const int q = row % Sc;
    float4* p4 = (float4*)(attn + (size_t)row * Sc);
    const int tid = threadIdx.x;
    const int qg = q >> 2;                // last active float4 group

    __shared__ float red[256];
    float4 v[2];
    bool act[2];

    float m = -1e30f;
#pragma unroll
    for (int i = 0; i < 2; i++) {
        int k4 = tid + (i << 8);
        act[i] = (k4 <= qg);
        if (act[i]) {
            float4 s = p4[k4];
            int kb = k4 << 2;
            if (kb + 1 > q) s.y = -1e30f;
            if (kb + 2 > q) s.z = -1e30f;
            if (kb + 3 > q) s.w = -1e30f;
            v[i] = s;
            m = fmaxf(m, fmaxf(fmaxf(s.x, s.y), fmaxf(s.z, s.w)));
        }
    }
    red[tid] = m;
    __syncthreads();
    for (int s = 128; s > 0; s >>= 1) {
        if (tid < s) red[tid] = fmaxf(red[tid], red[tid + s]);
        __syncthreads();
    }
    m = red[0];
    __syncthreads();

    float sum = 0.f;
#pragma unroll
    for (int i = 0; i < 2; i++) {
        if (act[i]) {
            v[i].x = expf(v[i].x - m);
            v[i].y = expf(v[i].y - m);
            v[i].z = expf(v[i].z - m);
            v[i].w = expf(v[i].w - m);
            sum += (v[i].x + v[i].y) + (v[i].z + v[i].w);
        }
    }
    red[tid] = sum;
    __syncthreads();
    for (int s = 128; s > 0; s >>= 1) {
        if (tid < s) red[tid] += red[tid + s];
        __syncthreads();
    }
    float inv = 1.0f / red[0];

    uint2* ah2 = (uint2*)(ah + (size_t)row * Sc);
#pragma unroll
    for (int i = 0; i < 2; i++) {
        int k4 = tid + (i << 8);
        if (act[i]) {
            float4 o;
            o.x = v[i].x * inv; o.y = v[i].y * inv;
            o.z = v[i].z * inv; o.w = v[i].w * inv;
            p4[k4] = o;
            __half2 hA = __floats2half2_rn(o.x, o.y);
            __half2 hB = __floats2half2_rn(o.z, o.w);
            ah2[k4] = make_uint2(*(uint32_t*)&hA, *(uint32_t*)&hB);
        } else {
            p4[k4] = make_float4(0.f, 0.f, 0.f, 0.f);
            ah2[k4] = make_uint2(0u, 0u);
        }
    }
}

// ---------------------------------------------------------------------------
extern "C" void kernel_launch(void* const* d_in, const int* in_sizes, int n_in,
                              void* d_out, int out_size)
{
    const float *hidden, *Wq, *Wk, *Wv, *Wo;
    const int* pos_ids;
    const int POS_E = Bc * Sc;

    if (n_in >= 7 && in_sizes[6] == POS_E) {
        Wk = (const float*)d_in[0]; Wo = (const float*)d_in[1];
        Wq = (const float*)d_in[2]; Wv = (const float*)d_in[3];
        hidden = (const float*)d_in[5];
        pos_ids = (const int*)d_in[6];
    } else {
        hidden = (const float*)d_in[0];
        pos_ids = (const int*)d_in[2];
        Wq = (const float*)d_in[3]; Wk = (const float*)d_in[4];
        Wv = (const float*)d_in[5]; Wo = (const float*)d_in[6];
    }

    float* out = (float*)d_out;
    const long OUT_E = (long)Bc * Sc * Dc;
    const long ATT_E = (long)Bc * Hc * Sc * Sc;

    float *QKV, *ATTN_FB;
    cudaGetSymbolAddress((void**)&QKV, g_QKV);
    cudaGetSymbolAddress((void**)&ATTN_FB, g_attn_fb);

    __half *hid_h, *wqkv_h, *wo_h;
    __half *q_h, *k_h, *vt_h, *at_h, *cx_h;
    cudaGetSymbolAddress((void**)&hid_h, g_hid_h);
    cudaGetSymbolAddress((void**)&wqkv_h, g_wqkv_h);
    cudaGetSymbolAddress((void**)&wo_h, g_wo_h);
    cudaGetSymbolAddress((void**)&q_h, g_q_h);
    cudaGetSymbolAddress((void**)&k_h, g_k_h);
    cudaGetSymbolAddress((void**)&vt_h, g_vt_h);
    cudaGetSymbolAddress((void**)&at_h, g_at_h);
    cudaGetSymbolAddress((void**)&cx_h, g_cx_h);

    float* attn = ((long)out_size >= OUT_E + ATT_E) ? out + OUT_E : ATTN_FB;

    cudaFuncSetAttribute(hgemm2<0, 1>, cudaFuncAttributeMaxDynamicSharedMemorySize, SMEMSZ);
    cudaFuncSetAttribute(hgemm2<1, 1>, cudaFuncAttributeMaxDynamicSharedMemorySize, SMEMSZ);
    cudaFuncSetAttribute(hgemm2<2, 1>, cudaFuncAttributeMaxDynamicSharedMemorySize, SMEMSZ);

    const int MR = Bc * Sc;  // 4096

    // input splits: all hi-only
    split_kernel<<<4096, 256>>>(hidden, hid_h, (__half*)0, (long)MR * Dc);
    split_kernel<<<2048, 256>>>(Wq, wqkv_h,                    (__half*)0, (long)NQ * Dc);
    split_kernel<<<512,  256>>>(Wk, wqkv_h + (size_t)NQ * Dc,  (__half*)0, (long)NKV * Dc);
    split_kernel<<<512,  256>>>(Wv, wqkv_h + (size_t)(NQ + NKV) * Dc, (__half*)0, (long)NKV * Dc);
    split_kernel<<<2048, 256>>>(Wo, wo_h, (__half*)0, (long)Dc * NQ);

    // fused QKV projection: [4096, 2560] fp32, 1-pass
    {
        dim3 g(NQKV / 128, MR / 128, 1);
        hgemm2<0, 1><<<g, 512, SMEMSZ>>>(hid_h, (__half*)0, wqkv_h, QKV,
            (__half*)0, (__half*)0,
            Dc, Dc, Dc, NQKV, 0, 0, 0, 0, 0, 0, 1, 1.0f);
    }
    // RoPE -> fp16 hi only (Q from cols 0..2047, K from cols 2048..2303)
    {
        long totQ = (long)Bc * Sc * Hc * 128;
        long totK = (long)Bc * Sc * 1 * 128;
        rope_fp16<<<(int)((totQ + 255) / 256), 256>>>(QKV, NQKV, 0,
            q_h, pos_ids, Hc, totQ);
        rope_fp16<<<(int)((totK + 255) / 256), 256>>>(QKV, NQKV, 2048,
            k_h, pos_ids, 1, totK);
    }
    // V transpose (cols 2304..2559 -> vt_h[b][d][s])
    {
        dim3 g(Sc / 32, NKV / 32, Bc);
        vtrans_kernel<<<g, dim3(32, 8)>>>(QKV, vt_h);
    }
    // scores = (1/16) Q K^T, 1-pass, causal tile skip
    {
        dim3 g(Sc / 128, Sc / 128, Bc * Hc);
        hgemm2<1, 1><<<g, 512, SMEMSZ>>>(q_h, (__half*)0, k_h, attn,
            (__half*)0, (__half*)0,
            HDc, NQ, NKV, Sc,
            (long)Sc * NQ, (long)HDc,
            (long)Sc * NKV, 0,
            (long)Hc * Sc * Sc, (long)Sc * Sc,
            Hc, 1.0f / 16.0f);
    }
    // softmax (analytic causal) + fp16-hi split
    softmax_split<<<Bc * Hc * Sc, 256>>>(attn, at_h);
    // ctx = attn @ Vt^T, 1-pass, kEnd truncation — fp16 hi emitted
    {
        dim3 g(NKV / 128, Sc / 128, Bc * Hc);
        hgemm2<2, 1><<<g, 512, SMEMSZ>>>(at_h, (__half*)0, vt_h,
            (float*)0, cx_h, (__half*)0,
            Sc, Sc, Sc, NQ,
            (long)Hc * Sc * Sc, (long)Sc * Sc,
            (long)NKV * Sc, 0,
            (long)Sc * NQ, (long)HDc,
            Hc, 1.0f);
    }
    // out = ctx @ Wo^T, 1-pass
    {
        dim3 g(Dc / 128, MR / 128, 1);
        hgemm2<0, 1><<<g, 512, SMEMSZ>>>(cx_h, (__half*)0, wo_h, out,
            (__half*)0, (__half*)0,
            NQ, NQ, NQ, Dc, 0, 0, 0, 0, 0, 0, 1, 1.0f);
    }
}

// round 16
// speedup vs baseline: 1.1199x; 1.1199x over previous
#include <cuda_runtime.h>
#include <cuda_fp16.h>
#include <math.h>
#include <stdint.h>

// Problem constants
#define Bc 2
#define Sc 2048
#define Dc 2048
#define Hc 8
#define HDc 256
#define NQ 2048           // H*HD
#define NKV 256           // KVH*HD
#define NQKV 2560         // NQ + 2*NKV

// ---------------- scratch (device globals; allocation-free rule) ------------
__device__ float g_QKV[(size_t)Bc*Sc*NQKV];     // [4096, 2560]: Q | K | V
__device__ float g_attn_fb[(size_t)Bc*Hc*Sc*Sc];

__device__ __half g_hid_h[(size_t)Bc*Sc*Dc];
__device__ __half g_wqkv_h[(size_t)NQKV*Dc];    // [2560, 2048]: Wq;Wk;Wv hi
__device__ __half g_wo_h[(size_t)Dc*NQ];
__device__ __half g_q_h[(size_t)Bc*Sc*NQ];
__device__ __half g_k_h[(size_t)Bc*Sc*NKV];
__device__ __half g_vt_h[(size_t)Bc*NKV*Sc];    // [b][d][s]
__device__ __half g_at_h[(size_t)Bc*Hc*Sc*Sc];
__device__ __half g_cx_h[(size_t)Bc*Sc*NQ];

// ---------------- warp-MMA helpers ------------------------------------------
__device__ __forceinline__ uint32_t smem_u32(const void* p) {
    uint32_t a;
    asm("{ .reg .u64 t; cvta.to.shared.u64 t, %1; cvt.u32.u64 %0, t; }"
        : "=r"(a) : "l"(p));
    return a;
}

#define LDSM4(r, a) \
    asm volatile("ldmatrix.sync.aligned.m8n8.x4.shared.b16 {%0,%1,%2,%3}, [%4];" \
        : "=r"((r)[0]), "=r"((r)[1]), "=r"((r)[2]), "=r"((r)[3]) : "r"(a))

#define MMA16816(d, a, b0, b1) \
    asm volatile("mma.sync.aligned.m16n8k16.row.col.f32.f16.f16.f32 " \
        "{%0,%1,%2,%3}, {%4,%5,%6,%7}, {%8,%9}, {%0,%1,%2,%3};" \
        : "+f"((d)[0]), "+f"((d)[1]), "+f"((d)[2]), "+f"((d)[3]) \
        : "r"((a)[0]), "r"((a)[1]), "r"((a)[2]), "r"((a)[3]), \
          "r"(b0), "r"(b1))

#define CP16(s, g) \
    asm volatile("cp.async.ca.shared.global [%0], [%1], 16;" :: "r"(s), "l"(g))

// K-chunk 64; padded tile: 128 rows x 72 half (144B stride).
// ldmatrix 8-row phases hit banks (144r/4)%32 = 4r%32 -> distinct, conflict-free.
#define BK   64
#define PADW 72
#define TB   (128 * PADW * 2)        // 18432 bytes per tile
#define STAGEB (2 * TB)              // A, B (all GEMMs 1-pass)
#define SMEMSZ (2 * STAGEB)          // 73728

__device__ __forceinline__ void fsplit(float v, __half& h, __half& l) {
    h = __float2half_rn(v);
    l = __float2half_rn(v - __half2float(h));
}

// ---------------------------------------------------------------------------
// fp16 (hi-only) NT GEMM on tensor cores, 2-stage cp.async double-buffer,
// K-chunk 64. out = alpha * Ah @ Bh^T.
// 128x128 tile, 512 threads = 16 warps (4m x 4n), warp 32x32.
// CAUSAL: 0 none; 1 skip tiles fully above diagonal; 2 kEnd = m0+128.
// C (fp32) / Chp (fp16) may independently be null.
// ---------------------------------------------------------------------------
template<int CAUSAL>
__global__ void __launch_bounds__(512)
hgemm1(const __half* __restrict__ Ah, const __half* __restrict__ Bh,
       float* __restrict__ C, __half* __restrict__ Chp,
       int K, int lda, int ldb, int ldc,
       long sAb, long sAh_, long sBb, long sBh_, long sCb, long sCh_,
       int Hdiv, float alpha)
{
    const int z = blockIdx.z;
    const int b = z / Hdiv, h = z % Hdiv;
    Ah += (long)b * sAb + (long)h * sAh_;
    Bh += (long)b * sBb + (long)h * sBh_;
    const long offC = (long)b * sCb + (long)h * sCh_;
    if (C)   C   += offC;
    if (Chp) Chp += offC;

    const int m0 = blockIdx.y * 128;
    const int n0 = blockIdx.x * 128;
    if (CAUSAL == 1 && n0 > m0 + 127) return;
    const int kEnd = (CAUSAL == 2) ? min(K, m0 + 128) : K;

    extern __shared__ char sm[];
    const uint32_t sb = smem_u32(sm);

    const int tid = threadIdx.x;
    const int wid = tid >> 5;
    const int lane = tid & 31;
    const int wm = wid & 3;
    const int wn = wid >> 2;

    // loader: each thread 2x 16B per tile (128 rows x 64 halves)
    const int lr = tid >> 2;             // 0..127
    const int lc = (tid & 3) * 16;       // 0,16,32,48
    const uint32_t soff = (uint32_t)(lr * (PADW * 2) + lc * 2);

    const int quad = lane >> 3;
    const int a_row = wm * 32 + (lane & 7) + (quad & 1) * 8;
    const int a_col = (quad >> 1) * 8;
    const int b_row = wn * 32 + (lane & 7) + (quad >> 1) * 8;
    const int b_col = (quad & 1) * 8;

    float acc[2][4][4];
#pragma unroll
    for (int i = 0; i < 2; i++)
#pragma unroll
        for (int j = 0; j < 4; j++)
#pragma unroll
            for (int c = 0; c < 4; c++) acc[i][j][c] = 0.f;

    const int nCh = kEnd / BK;

    auto issue = [&](int st, int k0) {
        uint32_t s0 = sb + st * STAGEB + soff;
        size_t ga = (size_t)(m0 + lr) * lda + k0 + lc;
        size_t gb = (size_t)(n0 + lr) * ldb + k0 + lc;
        CP16(s0,           Ah + ga);
        CP16(s0 + 16,      Ah + ga + 8);
        CP16(s0 + TB,      Bh + gb);
        CP16(s0 + TB + 16, Bh + gb + 8);
        asm volatile("cp.async.commit_group;");
    };

    issue(0, 0);
    for (int i = 0; i < nCh; i++) {
        if (i + 1 < nCh) {
            issue((i + 1) & 1, (i + 1) * BK);
            asm volatile("cp.async.wait_group 1;");
        } else {
            asm volatile("cp.async.wait_group 0;");
        }
        __syncthreads();

        const uint32_t stb = sb + (i & 1) * STAGEB;
#pragma unroll
        for (int ks = 0; ks < 4; ks++) {
            uint32_t af[2][4];          // [mt]
            uint32_t bfr[2][4];         // [bt]
#pragma unroll
            for (int mt = 0; mt < 2; mt++) {
                uint32_t addr = stb +
                    ((uint32_t)((a_row + mt * 16) * PADW + ks * 16 + a_col) << 1);
                LDSM4(af[mt], addr);
            }
#pragma unroll
            for (int bt = 0; bt < 2; bt++) {
                uint32_t addr = stb + TB +
                    ((uint32_t)((b_row + bt * 16) * PADW + ks * 16 + b_col) << 1);
                LDSM4(bfr[bt], addr);
            }
#pragma unroll
            for (int mt = 0; mt < 2; mt++)
#pragma unroll
                for (int nt = 0; nt < 4; nt++) {
                    uint32_t b0 = bfr[nt >> 1][(nt & 1) * 2];
                    uint32_t b1 = bfr[nt >> 1][(nt & 1) * 2 + 1];
                    MMA16816(acc[mt][nt], af[mt], b0, b1);
                }
        }
        __syncthreads();
    }

    // epilogue
    const int g = lane >> 2;
    const int tc = lane & 3;
#pragma unroll
    for (int mt = 0; mt < 2; mt++) {
#pragma unroll
        for (int nt = 0; nt < 4; nt++) {
            int row = m0 + wm * 32 + mt * 16 + g;
            int col = n0 + wn * 32 + nt * 8 + tc * 2;
            float v[4];
            v[0] = acc[mt][nt][0] * alpha;
            v[1] = acc[mt][nt][1] * alpha;
            v[2] = acc[mt][nt][2] * alpha;
            v[3] = acc[mt][nt][3] * alpha;
#pragma unroll
            for (int e = 0; e < 4; e++) {
                int r = row + (e >> 1) * 8;
                int cl = col + (e & 1);
                size_t idx = (size_t)r * ldc + cl;
                if (C) C[idx] = v[e];
                if (Chp) Chp[idx] = __float2half_rn(v[e]);
            }
        }
    }
}

// ---------------------------------------------------------------------------
// vectorized fp32 -> fp16 hi split. n % 4 == 0.
// ---------------------------------------------------------------------------
__global__ void split_kernel(const float* __restrict__ x,
                             __half* __restrict__ hi, long n)
{
    long n4 = n >> 2;
    for (long i = (long)blockIdx.x * 256 + threadIdx.x; i < n4;
         i += (long)gridDim.x * 256) {
        float4 v = ((const float4*)x)[i];
        __half2 hA = __floats2half2_rn(v.x, v.y);
        __half2 hB = __floats2half2_rn(v.z, v.w);
        ((uint2*)hi)[i] = make_uint2(*(uint32_t*)&hA, *(uint32_t*)&hB);
    }
}

// ---------------------------------------------------------------------------
// RoPE -> fp16 (hi only). Reads x[(b*S+s)*ldx + col0 + h*256 + d]; writes
// packed [(b*S+s), NH*256] layout.
// ---------------------------------------------------------------------------
__global__ void rope_fp16(const float* __restrict__ x, int ldx, int col0,
                          __half* __restrict__ hi,
                          const int* __restrict__ pos_ids, int NH, long total)
{
    long idx = (long)blockIdx.x * 256 + threadIdx.x;
    if (idx >= total) return;
    int d = (int)(idx & 127);
    long t = idx >> 7;
    int h = (int)(t % NH); t /= NH;
    int s = (int)(t % Sc);
    int b = (int)(t / Sc);

    float p = (float)pos_ids[b * Sc + s];
    float invf = exp2f(-0.103810252965736f * (float)d);
    double ang = (double)p * (double)invf;
    double kq = nearbyint(ang * 0.15915494309189535);
    float r = (float)(ang - kq * 6.283185307179586);
    float sn, c;
    sincosf(r, &sn, &c);

    size_t inb = (size_t)(b * Sc + s) * ldx + col0 + h * 256;
    float x1 = x[inb + d];
    float x2 = x[inb + 128 + d];
    float r1 = x1 * c - x2 * sn;
    float r2 = x2 * c + x1 * sn;

    size_t base = ((size_t)(b * Sc + s) * NH + h) * 256;
    hi[base + d]       = __float2half_rn(r1);
    hi[base + 128 + d] = __float2half_rn(r2);
}

// ---------------------------------------------------------------------------
// V transpose: vt[b][d][s] = fp16(QKV[(b*S+s)*NQKV + 2304 + d])
// ---------------------------------------------------------------------------
__global__ void vtrans_kernel(const float* __restrict__ qkv,
                              __half* __restrict__ vt)
{
    __shared__ float tile[32][33];
    const int b = blockIdx.z;
    const int s0 = blockIdx.x * 32;
    const int d0 = blockIdx.y * 32;
    const int tx = threadIdx.x, ty = threadIdx.y;
#pragma unroll
    for (int j = 0; j < 4; j++) {
        int s = s0 + ty + j * 8;
        tile[ty + j * 8][tx] = qkv[(size_t)(b * Sc + s) * NQKV + 2304 + d0 + tx];
    }
    __syncthreads();
#pragma unroll
    for (int j = 0; j < 4; j++) {
        int d = d0 + ty + j * 8;
        vt[((size_t)b * NKV + d) * Sc + s0 + tx] =
            __float2half_rn(tile[tx][ty + j * 8]);
    }
}

// ---------------------------------------------------------------------------
// Vectorized causal softmax (analytic mask; verified exact vs mask input).
// k>q entries get -1e30 -> exp underflows to exact 0. Uses __expf (hw ex2).
// Emits fp16 hi.
// ---------------------------------------------------------------------------
__global__ void __launch_bounds__(256)
softmax_split(float* __restrict__ attn, __half* __restrict__ ah)
{
    const int row = blockIdx.x;           // (b*H + h)*S + q
    const int q = row % Sc;
    float4* p4 = (float4*)(attn + (size_t)row * Sc);
    const int tid = threadIdx.x;
    const int qg = q >> 2;                // last active float4 group

    __shared__ float red[256];
    float4 v[2];
    bool act[2];

    float m = -1e30f;
#pragma unroll
    for (int i = 0; i < 2; i++) {
        int k4 = tid + (i << 8);
        act[i] = (k4 <= qg);
        if (act[i]) {
            float4 s = p4[k4];
            int kb = k4 << 2;
            if (kb + 1 > q) s.y = -1e30f;
            if (kb + 2 > q) s.z = -1e30f;
            if (kb + 3 > q) s.w = -1e30f;
            v[i] = s;
            m = fmaxf(m, fmaxf(fmaxf(s.x, s.y), fmaxf(s.z, s.w)));
        }
    }
    red[tid] = m;
    __syncthreads();
    for (int s = 128; s > 0; s >>= 1) {
        if (tid < s) red[tid] = fmaxf(red[tid], red[tid + s]);
        __syncthreads();
    }
    m = red[0];
    __syncthreads();

    float sum = 0.f;
#pragma unroll
    for (int i = 0; i < 2; i++) {
        if (act[i]) {
            v[i].x = __expf(v[i].x - m);
            v[i].y = __expf(v[i].y - m);
            v[i].z = __expf(v[i].z - m);
            v[i].w = __expf(v[i].w - m);
            sum += (v[i].x + v[i].y) + (v[i].z + v[i].w);
        }
    }
    red[tid] = sum;
    __syncthreads();
    for (int s = 128; s > 0; s >>= 1) {
        if (tid < s) red[tid] += red[tid + s];
        __syncthreads();
    }
    float inv = 1.0f / red[0];

    uint2* ah2 = (uint2*)(ah + (size_t)row * Sc);
#pragma unroll
    for (int i = 0; i < 2; i++) {
        int k4 = tid + (i << 8);
        if (act[i]) {
            float4 o;
            o.x = v[i].x * inv; o.y = v[i].y * inv;
            o.z = v[i].z * inv; o.w = v[i].w * inv;
            p4[k4] = o;
            __half2 hA = __floats2half2_rn(o.x, o.y);
            __half2 hB = __floats2half2_rn(o.z, o.w);
            ah2[k4] = make_uint2(*(uint32_t*)&hA, *(uint32_t*)&hB);
        } else {
            p4[k4] = make_float4(0.f, 0.f, 0.f, 0.f);
            ah2[k4] = make_uint2(0u, 0u);
        }
    }
}

// ---------------------------------------------------------------------------
extern "C" void kernel_launch(void* const* d_in, const int* in_sizes, int n_in,
                              void* d_out, int out_size)
{
    const float *hidden, *Wq, *Wk, *Wv, *Wo;
    const int* pos_ids;
    const int POS_E = Bc * Sc;

    if (n_in >= 7 && in_sizes[6] == POS_E) {
        Wk = (const float*)d_in[0]; Wo = (const float*)d_in[1];
        Wq = (const float*)d_in[2]; Wv = (const float*)d_in[3];
        hidden = (const float*)d_in[5];
        pos_ids = (const int*)d_in[6];
    } else {
        hidden = (const float*)d_in[0];
        pos_ids = (const int*)d_in[2];
        Wq = (const float*)d_in[3]; Wk = (const float*)d_in[4];
        Wv = (const float*)d_in[5]; Wo = (const float*)d_in[6];
    }

    float* out = (float*)d_out;
    const long OUT_E = (long)Bc * Sc * Dc;
    const long ATT_E = (long)Bc * Hc * Sc * Sc;

    float *QKV, *ATTN_FB;
    cudaGetSymbolAddress((void**)&QKV, g_QKV);
    cudaGetSymbolAddress((void**)&ATTN_FB, g_attn_fb);

    __half *hid_h, *wqkv_h, *wo_h;
    __half *q_h, *k_h, *vt_h, *at_h, *cx_h;
    cudaGetSymbolAddress((void**)&hid_h, g_hid_h);
    cudaGetSymbolAddress((void**)&wqkv_h, g_wqkv_h);
    cudaGetSymbolAddress((void**)&wo_h, g_wo_h);
    cudaGetSymbolAddress((void**)&q_h, g_q_h);
    cudaGetSymbolAddress((void**)&k_h, g_k_h);
    cudaGetSymbolAddress((void**)&vt_h, g_vt_h);
    cudaGetSymbolAddress((void**)&at_h, g_at_h);
    cudaGetSymbolAddress((void**)&cx_h, g_cx_h);

    float* attn = ((long)out_size >= OUT_E + ATT_E) ? out + OUT_E : ATTN_FB;

    cudaFuncSetAttribute(hgemm1<0>, cudaFuncAttributeMaxDynamicSharedMemorySize, SMEMSZ);
    cudaFuncSetAttribute(hgemm1<1>, cudaFuncAttributeMaxDynamicSharedMemorySize, SMEMSZ);
    cudaFuncSetAttribute(hgemm1<2>, cudaFuncAttributeMaxDynamicSharedMemorySize, SMEMSZ);

    const int MR = Bc * Sc;  // 4096

    // input splits: all hi-only
    split_kernel<<<4096, 256>>>(hidden, hid_h, (long)MR * Dc);
    split_kernel<<<2048, 256>>>(Wq, wqkv_h,                    (long)NQ * Dc);
    split_kernel<<<512,  256>>>(Wk, wqkv_h + (size_t)NQ * Dc,  (long)NKV * Dc);
    split_kernel<<<512,  256>>>(Wv, wqkv_h + (size_t)(NQ + NKV) * Dc, (long)NKV * Dc);
    split_kernel<<<2048, 256>>>(Wo, wo_h, (long)Dc * NQ);

    // fused QKV projection: [4096, 2560] fp32
    {
        dim3 g(NQKV / 128, MR / 128, 1);
        hgemm1<0><<<g, 512, SMEMSZ>>>(hid_h, wqkv_h, QKV, (__half*)0,
            Dc, Dc, Dc, NQKV, 0, 0, 0, 0, 0, 0, 1, 1.0f);
    }
    // RoPE -> fp16 hi only (Q from cols 0..2047, K from cols 2048..2303)
    {
        long totQ = (long)Bc * Sc * Hc * 128;
        long totK = (long)Bc * Sc * 1 * 128;
        rope_fp16<<<(int)((totQ + 255) / 256), 256>>>(QKV, NQKV, 0,
            q_h, pos_ids, Hc, totQ);
        rope_fp16<<<(int)((totK + 255) / 256), 256>>>(QKV, NQKV, 2048,
            k_h, pos_ids, 1, totK);
    }
    // V transpose (cols 2304..2559 -> vt_h[b][d][s])
    {
        dim3 g(Sc / 32, NKV / 32, Bc);
        vtrans_kernel<<<g, dim3(32, 8)>>>(QKV, vt_h);
    }
    // scores = (1/16) Q K^T, causal tile skip
    {
        dim3 g(Sc / 128, Sc / 128, Bc * Hc);
        hgemm1<1><<<g, 512, SMEMSZ>>>(q_h, k_h, attn, (__half*)0,
            HDc, NQ, NKV, Sc,
            (long)Sc * NQ, (long)HDc,
            (long)Sc * NKV, 0,
            (long)Hc * Sc * Sc, (long)Sc * Sc,
            Hc, 1.0f / 16.0f);
    }
    // softmax (analytic causal) + fp16-hi split
    softmax_split<<<Bc * Hc * Sc, 256>>>(attn, at_h);
    // ctx = attn @ Vt^T, kEnd truncation — fp16 hi emitted
    {
        dim3 g(NKV / 128, Sc / 128, Bc * Hc);
        hgemm1<2><<<g, 512, SMEMSZ>>>(at_h, vt_h, (float*)0, cx_h,
            Sc, Sc, Sc, NQ,
            (long)Hc * Sc * Sc, (long)Sc * Sc,
            (long)NKV * Sc, 0,
            (long)Sc * NQ, (long)HDc,
            Hc, 1.0f);
    }
    // out = ctx @ Wo^T
    {
        dim3 g(Dc / 128, MR / 128, 1);
        hgemm1<0><<<g, 512, SMEMSZ>>>(cx_h, wo_h, out, (__half*)0,
            NQ, NQ, NQ, Dc, 0, 0, 0, 0, 0, 0, 1, 1.0f);
    }
}

// round 17
// speedup vs baseline: 1.1964x; 1.0684x over previous
#include <cuda_runtime.h>
#include <cuda_fp16.h>
#include <math.h>
#include <stdint.h>

// Problem constants
#define Bc 2
#define Sc 2048
#define Dc 2048
#define Hc 8
#define HDc 256
#define NQ 2048           // H*HD
#define NKV 256           // KVH*HD
#define NQKV 2560         // NQ + 2*NKV

// ---------------- scratch (device globals; allocation-free rule) ------------
__device__ float g_QKV[(size_t)Bc*Sc*NQKV];     // [4096, 2560]: Q | K | V
__device__ float g_attn_fb[(size_t)Bc*Hc*Sc*Sc];

__device__ __half g_hid_h[(size_t)Bc*Sc*Dc];
__device__ __half g_wqkv_h[(size_t)NQKV*Dc];    // [2560, 2048]: Wq;Wk;Wv hi
__device__ __half g_wo_h[(size_t)Dc*NQ];
__device__ __half g_q_h[(size_t)Bc*Sc*NQ];
__device__ __half g_k_h[(size_t)Bc*Sc*NKV];
__device__ __half g_vt_h[(size_t)Bc*NKV*Sc];    // [b][d][s]
__device__ __half g_at_h[(size_t)Bc*Hc*Sc*Sc];
__device__ __half g_cx_h[(size_t)Bc*Sc*NQ];

// ---------------- warp-MMA helpers ------------------------------------------
__device__ __forceinline__ uint32_t smem_u32(const void* p) {
    uint32_t a;
    asm("{ .reg .u64 t; cvta.to.shared.u64 t, %1; cvt.u32.u64 %0, t; }"
        : "=r"(a) : "l"(p));
    return a;
}

#define LDSM4(r, a) \
    asm volatile("ldmatrix.sync.aligned.m8n8.x4.shared.b16 {%0,%1,%2,%3}, [%4];" \
        : "=r"((r)[0]), "=r"((r)[1]), "=r"((r)[2]), "=r"((r)[3]) : "r"(a))

#define MMA16816(d, a, b0, b1) \
    asm volatile("mma.sync.aligned.m16n8k16.row.col.f32.f16.f16.f32 " \
        "{%0,%1,%2,%3}, {%4,%5,%6,%7}, {%8,%9}, {%0,%1,%2,%3};" \
        : "+f"((d)[0]), "+f"((d)[1]), "+f"((d)[2]), "+f"((d)[3]) \
        : "r"((a)[0]), "r"((a)[1]), "r"((a)[2]), "r"((a)[3]), \
          "r"(b0), "r"(b1))

#define CP16(s, g) \
    asm volatile("cp.async.ca.shared.global [%0], [%1], 16;" :: "r"(s), "l"(g))

// K-chunk 64; padded tile: 128 rows x 72 half (144B stride).
// ldmatrix 8-row phases hit banks 4r%32 -> distinct, conflict-free.
#define BK   64
#define PADW 72
#define TB   (128 * PADW * 2)        // 18432 bytes per tile
#define STAGEB (2 * TB)              // A, B
#define SMEMSZ (2 * STAGEB)          // 73728  (x2 CTAs = 147456 <= 228KB)

// ---------------------------------------------------------------------------
// fp16 (hi-only) NT GEMM on tensor cores, 2-stage cp.async double-buffer,
// K-chunk 64, 2 CTAs/SM. out = alpha * Ah @ Bh^T.
// 128x128 tile, 512 threads = 16 warps (4m x 4n), warp 32x32.
// CAUSAL: 0 none; 1 skip tiles fully above diagonal; 2 kEnd = m0+128.
// C (fp32) / Chp (fp16) may independently be null.
// ---------------------------------------------------------------------------
template<int CAUSAL>
__global__ void __launch_bounds__(512, 2)
hgemm1(const __half* __restrict__ Ah, const __half* __restrict__ Bh,
       float* __restrict__ C, __half* __restrict__ Chp,
       int K, int lda, int ldb, int ldc,
       long sAb, long sAh_, long sBb, long sBh_, long sCb, long sCh_,
       int Hdiv, float alpha)
{
    const int z = blockIdx.z;
    const int b = z / Hdiv, h = z % Hdiv;
    Ah += (long)b * sAb + (long)h * sAh_;
    Bh += (long)b * sBb + (long)h * sBh_;
    const long offC = (long)b * sCb + (long)h * sCh_;
    if (C)   C   += offC;
    if (Chp) Chp += offC;

    const int m0 = blockIdx.y * 128;
    const int n0 = blockIdx.x * 128;
    if (CAUSAL == 1 && n0 > m0 + 127) return;
    const int kEnd = (CAUSAL == 2) ? min(K, m0 + 128) : K;

    extern __shared__ char sm[];
    const uint32_t sb = smem_u32(sm);

    const int tid = threadIdx.x;
    const int wid = tid >> 5;
    const int lane = tid & 31;
    const int wm = wid & 3;
    const int wn = wid >> 2;

    const int lr = tid >> 2;             // 0..127
    const int lc = (tid & 3) * 16;       // 0,16,32,48
    const uint32_t soff = (uint32_t)(lr * (PADW * 2) + lc * 2);

    const int quad = lane >> 3;
    const int a_row = wm * 32 + (lane & 7) + (quad & 1) * 8;
    const int a_col = (quad >> 1) * 8;
    const int b_row = wn * 32 + (lane & 7) + (quad >> 1) * 8;
    const int b_col = (quad & 1) * 8;

    float acc[2][4][4];
#pragma unroll
    for (int i = 0; i < 2; i++)
#pragma unroll
        for (int j = 0; j < 4; j++)
#pragma unroll
            for (int c = 0; c < 4; c++) acc[i][j][c] = 0.f;

    const int nCh = kEnd / BK;

    auto issue = [&](int st, int k0) {
        uint32_t s0 = sb + st * STAGEB + soff;
        size_t ga = (size_t)(m0 + lr) * lda + k0 + lc;
        size_t gb = (size_t)(n0 + lr) * ldb + k0 + lc;
        CP16(s0,           Ah + ga);
        CP16(s0 + 16,      Ah + ga + 8);
        CP16(s0 + TB,      Bh + gb);
        CP16(s0 + TB + 16, Bh + gb + 8);
        asm volatile("cp.async.commit_group;");
    };

    issue(0, 0);
    for (int i = 0; i < nCh; i++) {
        if (i + 1 < nCh) {
            issue((i + 1) & 1, (i + 1) * BK);
            asm volatile("cp.async.wait_group 1;");
        } else {
            asm volatile("cp.async.wait_group 0;");
        }
        __syncthreads();

        const uint32_t stb = sb + (i & 1) * STAGEB;
#pragma unroll
        for (int ks = 0; ks < 4; ks++) {
            uint32_t af[2][4];
            uint32_t bfr[2][4];
#pragma unroll
            for (int mt = 0; mt < 2; mt++) {
                uint32_t addr = stb +
                    ((uint32_t)((a_row + mt * 16) * PADW + ks * 16 + a_col) << 1);
                LDSM4(af[mt], addr);
            }
#pragma unroll
            for (int bt = 0; bt < 2; bt++) {
                uint32_t addr = stb + TB +
                    ((uint32_t)((b_row + bt * 16) * PADW + ks * 16 + b_col) << 1);
                LDSM4(bfr[bt], addr);
            }
#pragma unroll
            for (int mt = 0; mt < 2; mt++)
#pragma unroll
                for (int nt = 0; nt < 4; nt++) {
                    uint32_t b0 = bfr[nt >> 1][(nt & 1) * 2];
                    uint32_t b1 = bfr[nt >> 1][(nt & 1) * 2 + 1];
                    MMA16816(acc[mt][nt], af[mt], b0, b1);
                }
        }
        __syncthreads();
    }

    // epilogue (vectorized: float2 / packed half2 stores)
    const int g = lane >> 2;
    const int tc = lane & 3;
#pragma unroll
    for (int mt = 0; mt < 2; mt++) {
#pragma unroll
        for (int nt = 0; nt < 4; nt++) {
            int row = m0 + wm * 32 + mt * 16 + g;
            int col = n0 + wn * 32 + nt * 8 + tc * 2;
            float c0 = acc[mt][nt][0] * alpha;
            float c1 = acc[mt][nt][1] * alpha;
            float c2 = acc[mt][nt][2] * alpha;
            float c3 = acc[mt][nt][3] * alpha;
            size_t i0 = (size_t)row * ldc + col;
            size_t i1 = (size_t)(row + 8) * ldc + col;
            if (C) {
                *(float2*)&C[i0] = make_float2(c0, c1);
                *(float2*)&C[i1] = make_float2(c2, c3);
            }
            if (Chp) {
                __half2 h0 = __floats2half2_rn(c0, c1);
                __half2 h1 = __floats2half2_rn(c2, c3);
                *(uint32_t*)&Chp[i0] = *(uint32_t*)&h0;
                *(uint32_t*)&Chp[i1] = *(uint32_t*)&h1;
            }
        }
    }
}

// ---------------------------------------------------------------------------
// vectorized fp32 -> fp16 hi split. n % 4 == 0.
// ---------------------------------------------------------------------------
__global__ void split_kernel(const float* __restrict__ x,
                             __half* __restrict__ hi, long n)
{
    long n4 = n >> 2;
    for (long i = (long)blockIdx.x * 256 + threadIdx.x; i < n4;
         i += (long)gridDim.x * 256) {
        float4 v = ((const float4*)x)[i];
        __half2 hA = __floats2half2_rn(v.x, v.y);
        __half2 hB = __floats2half2_rn(v.z, v.w);
        ((uint2*)hi)[i] = make_uint2(*(uint32_t*)&hA, *(uint32_t*)&hB);
    }
}

// ---------------------------------------------------------------------------
// RoPE -> fp16 for BOTH Q and K in one launch.
// idx < totQ: Q (col0=0, NH=8, out q_h). else: K (col0=2048, NH=1, out k_h).
// ---------------------------------------------------------------------------
__global__ void rope_fp16_qk(const float* __restrict__ x,
                             __half* __restrict__ qh, __half* __restrict__ kh,
                             const int* __restrict__ pos_ids,
                             long totQ, long totAll)
{
    long idx = (long)blockIdx.x * 256 + threadIdx.x;
    if (idx >= totAll) return;

    int NH, col0;
    __half* out;
    long li;
    if (idx < totQ) { NH = Hc; col0 = 0; out = qh; li = idx; }
    else            { NH = 1; col0 = 2048; out = kh; li = idx - totQ; }

    int d = (int)(li & 127);
    long t = li >> 7;
    int h = (int)(t % NH); t /= NH;
    int s = (int)(t % Sc);
    int b = (int)(t / Sc);

    float p = (float)pos_ids[b * Sc + s];
    float invf = exp2f(-0.103810252965736f * (float)d);
    double ang = (double)p * (double)invf;
    double kq = nearbyint(ang * 0.15915494309189535);
    float r = (float)(ang - kq * 6.283185307179586);
    float sn, c;
    sincosf(r, &sn, &c);

    size_t inb = (size_t)(b * Sc + s) * NQKV + col0 + h * 256;
    float x1 = x[inb + d];
    float x2 = x[inb + 128 + d];
    float r1 = x1 * c - x2 * sn;
    float r2 = x2 * c + x1 * sn;

    size_t base = ((size_t)(b * Sc + s) * NH + h) * 256;
    out[base + d]       = __float2half_rn(r1);
    out[base + 128 + d] = __float2half_rn(r2);
}

// ---------------------------------------------------------------------------
// V transpose: vt[b][d][s] = fp16(QKV[(b*S+s)*NQKV + 2304 + d])
// ---------------------------------------------------------------------------
__global__ void vtrans_kernel(const float* __restrict__ qkv,
                              __half* __restrict__ vt)
{
    __shared__ float tile[32][33];
    const int b = blockIdx.z;
    const int s0 = blockIdx.x * 32;
    const int d0 = blockIdx.y * 32;
    const int tx = threadIdx.x, ty = threadIdx.y;
#pragma unroll
    for (int j = 0; j < 4; j++) {
        int s = s0 + ty + j * 8;
        tile[ty + j * 8][tx] = qkv[(size_t)(b * Sc + s) * NQKV + 2304 + d0 + tx];
    }
    __syncthreads();
#pragma unroll
    for (int j = 0; j < 4; j++) {
        int d = d0 + ty + j * 8;
        vt[((size_t)b * NKV + d) * Sc + s0 + tx] =
            __float2half_rn(tile[tx][ty + j * 8]);
    }
}

// ---------------------------------------------------------------------------
// Vectorized causal softmax (analytic mask; verified exact vs mask input).
// k>q entries get -1e30 -> exp underflows to exact 0. Uses __expf (hw ex2).
// Emits fp16 hi.
// ---------------------------------------------------------------------------
__global__ void __launch_bounds__(256)
softmax_split(float* __restrict__ attn, __half* __restrict__ ah)
{
    const int row = blockIdx.x;           // (b*H + h)*S + q
    const int q = row % Sc;
    float4* p4 = (float4*)(attn + (size_t)row * Sc);
    const int tid = threadIdx.x;
    const int qg = q >> 2;

    __shared__ float red[256];
    float4 v[2];
    bool act[2];

    float m = -1e30f;
#pragma unroll
    for (int i = 0; i < 2; i++) {
        int k4 = tid + (i << 8);
        act[i] = (k4 <= qg);
        if (act[i]) {
            float4 s = p4[k4];
            int kb = k4 << 2;
            if (kb + 1 > q) s.y = -1e30f;
            if (kb + 2 > q) s.z = -1e30f;
            if (kb + 3 > q) s.w = -1e30f;
            v[i] = s;
            m = fmaxf(m, fmaxf(fmaxf(s.x, s.y), fmaxf(s.z, s.w)));
        }
    }
    red[tid] = m;
    __syncthreads();
    for (int s = 128; s > 0; s >>= 1) {
        if (tid < s) red[tid] = fmaxf(red[tid], red[tid + s]);
        __syncthreads();
    }
    m = red[0];
    __syncthreads();

    float sum = 0.f;
#pragma unroll
    for (int i = 0; i < 2; i++) {
        if (act[i]) {
            v[i].x = __expf(v[i].x - m);
            v[i].y = __expf(v[i].y - m);
            v[i].z = __expf(v[i].z - m);
            v[i].w = __expf(v[i].w - m);
            sum += (v[i].x + v[i].y) + (v[i].z + v[i].w);
        }
    }
    red[tid] = sum;
    __syncthreads();
    for (int s = 128; s > 0; s >>= 1) {
        if (tid < s) red[tid] += red[tid + s];
        __syncthreads();
    }
    float inv = 1.0f / red[0];

    uint2* ah2 = (uint2*)(ah + (size_t)row * Sc);
#pragma unroll
    for (int i = 0; i < 2; i++) {
        int k4 = tid + (i << 8);
        if (act[i]) {
            float4 o;
            o.x = v[i].x * inv; o.y = v[i].y * inv;
            o.z = v[i].z * inv; o.w = v[i].w * inv;
            p4[k4] = o;
            __half2 hA = __floats2half2_rn(o.x, o.y);
            __half2 hB = __floats2half2_rn(o.z, o.w);
            ah2[k4] = make_uint2(*(uint32_t*)&hA, *(uint32_t*)&hB);
        } else {
            p4[k4] = make_float4(0.f, 0.f, 0.f, 0.f);
            ah2[k4] = make_uint2(0u, 0u);
        }
    }
}

// ---------------------------------------------------------------------------
extern "C" void kernel_launch(void* const* d_in, const int* in_sizes, int n_in,
                              void* d_out, int out_size)
{
    const float *hidden, *Wq, *Wk, *Wv, *Wo;
    const int* pos_ids;
    const int POS_E = Bc * Sc;

    if (n_in >= 7 && in_sizes[6] == POS_E) {
        Wk = (const float*)d_in[0]; Wo = (const float*)d_in[1];
        Wq = (const float*)d_in[2]; Wv = (const float*)d_in[3];
        hidden = (const float*)d_in[5];
        pos_ids = (const int*)d_in[6];
    } else {
        hidden = (const float*)d_in[0];
        pos_ids = (const int*)d_in[2];
        Wq = (const float*)d_in[3]; Wk = (const float*)d_in[4];
        Wv = (const float*)d_in[5]; Wo = (const float*)d_in[6];
    }

    float* out = (float*)d_out;
    const long OUT_E = (long)Bc * Sc * Dc;
    const long ATT_E = (long)Bc * Hc * Sc * Sc;

    float *QKV, *ATTN_FB;
    cudaGetSymbolAddress((void**)&QKV, g_QKV);
    cudaGetSymbolAddress((void**)&ATTN_FB, g_attn_fb);

    __half *hid_h, *wqkv_h, *wo_h;
    __half *q_h, *k_h, *vt_h, *at_h, *cx_h;
    cudaGetSymbolAddress((void**)&hid_h, g_hid_h);
    cudaGetSymbolAddress((void**)&wqkv_h, g_wqkv_h);
    cudaGetSymbolAddress((void**)&wo_h, g_wo_h);
    cudaGetSymbolAddress((void**)&q_h, g_q_h);
    cudaGetSymbolAddress((void**)&k_h, g_k_h);
    cudaGetSymbolAddress((void**)&vt_h, g_vt_h);
    cudaGetSymbolAddress((void**)&at_h, g_at_h);
    cudaGetSymbolAddress((void**)&cx_h, g_cx_h);

    float* attn = ((long)out_size >= OUT_E + ATT_E) ? out + OUT_E : ATTN_FB;

    cudaFuncSetAttribute(hgemm1<0>, cudaFuncAttributeMaxDynamicSharedMemorySize, SMEMSZ);
    cudaFuncSetAttribute(hgemm1<1>, cudaFuncAttributeMaxDynamicSharedMemorySize, SMEMSZ);
    cudaFuncSetAttribute(hgemm1<2>, cudaFuncAttributeMaxDynamicSharedMemorySize, SMEMSZ);

    const int MR = Bc * Sc;  // 4096

    // input splits: all hi-only
    split_kernel<<<4096, 256>>>(hidden, hid_h, (long)MR * Dc);
    split_kernel<<<2048, 256>>>(Wq, wqkv_h,                    (long)NQ * Dc);
    split_kernel<<<512,  256>>>(Wk, wqkv_h + (size_t)NQ * Dc,  (long)NKV * Dc);
    split_kernel<<<512,  256>>>(Wv, wqkv_h + (size_t)(NQ + NKV) * Dc, (long)NKV * Dc);
    split_kernel<<<2048, 256>>>(Wo, wo_h, (long)Dc * NQ);

    // fused QKV projection: [4096, 2560] fp32
    {
        dim3 g(NQKV / 128, MR / 128, 1);
        hgemm1<0><<<g, 512, SMEMSZ>>>(hid_h, wqkv_h, QKV, (__half*)0,
            Dc, Dc, Dc, NQKV, 0, 0, 0, 0, 0, 0, 1, 1.0f);
    }
    // RoPE -> fp16 (Q and K in one launch)
    {
        long totQ = (long)Bc * Sc * Hc * 128;
        long totK = (long)Bc * Sc * 1 * 128;
        long totAll = totQ + totK;
        rope_fp16_qk<<<(int)((totAll + 255) / 256), 256>>>(QKV, q_h, k_h,
            pos_ids, totQ, totAll);
    }
    // V transpose (cols 2304..2559 -> vt_h[b][d][s])
    {
        dim3 g(Sc / 32, NKV / 32, Bc);
        vtrans_kernel<<<g, dim3(32, 8)>>>(QKV, vt_h);
    }
    // scores = (1/16) Q K^T, causal tile skip
    {
        dim3 g(Sc / 128, Sc / 128, Bc * Hc);
        hgemm1<1><<<g, 512, SMEMSZ>>>(q_h, k_h, attn, (__half*)0,
            HDc, NQ, NKV, Sc,
            (long)Sc * NQ, (long)HDc,
            (long)Sc * NKV, 0,
            (long)Hc * Sc * Sc, (long)Sc * Sc,
            Hc, 1.0f / 16.0f);
    }
    // softmax (analytic causal) + fp16-hi split
    softmax_split<<<Bc * Hc * Sc, 256>>>(attn, at_h);
    // ctx = attn @ Vt^T, kEnd truncation — fp16 hi emitted
    {
        dim3 g(NKV / 128, Sc / 128, Bc * Hc);
        hgemm1<2><<<g, 512, SMEMSZ>>>(at_h, vt_h, (float*)0, cx_h,
            Sc, Sc, Sc, NQ,
            (long)Hc * Sc * Sc, (long)Sc * Sc,
            (long)NKV * Sc, 0,
            (long)Sc * NQ, (long)HDc,
            Hc, 1.0f);
    }
    // out = ctx @ Wo^T
    {
        dim3 g(Dc / 128, MR / 128, 1);
        hgemm1<0><<<g, 512, SMEMSZ>>>(cx_h, wo_h, out, (__half*)0,
            NQ, NQ, NQ, Dc, 0, 0, 0, 0, 0, 0, 1, 1.0f);
    }
}